// round 1
// baseline (speedup 1.0000x reference)
#include <cuda_runtime.h>
#include <cuda_bf16.h>

// G4 (9x9) at [0..80], G6 (13x13) at [81..249]
__device__ float g_G[256];

// ---------------------------------------------------------------------------
// Init kernel: builds the constant conjugator matrices G_l = Re(Q^H P d(pi/2) Q)
// entirely from closed forms (Wigner d formula + reference's Q), in fp64.
// ---------------------------------------------------------------------------
__global__ void init_G_kernel() {
    __shared__ double dmat[13 * 13];
    __shared__ double Qre[13 * 13], Qim[13 * 13];
    __shared__ double T2re[13 * 13], T2im[13 * 13];

    const double fact[14] = {1.0, 1.0, 2.0, 6.0, 24.0, 120.0, 720.0, 5040.0,
                             40320.0, 362880.0, 3628800.0, 39916800.0,
                             479001600.0, 6227020800.0};
    int tid = threadIdx.x;

    for (int li = 0; li < 2; li++) {
        const int l = (li == 0) ? 4 : 6;
        const int n = 2 * l + 1;
        const int off = (li == 0) ? 0 : 81;
        const double scale = (li == 0) ? (1.0 / 16.0) : (1.0 / 64.0); // 2^-l

        // --- Wigner small-d at beta = pi/2, d[mu', mu], mu = l+m ascending ---
        for (int e = tid; e < n * n; e += blockDim.x) {
            int mp = e / n - l;
            int m  = e % n - l;
            double pref = sqrt(fact[l + mp] * fact[l - mp] * fact[l + m] * fact[l - m]);
            int smin = (m - mp > 0) ? (m - mp) : 0;
            int smax = (l + m < l - mp) ? (l + m) : (l - mp);
            double sum = 0.0;
            for (int s = smin; s <= smax; s++) {
                double term = 1.0 / (fact[l + m - s] * fact[s] *
                                     fact[mp - m + s] * fact[l - mp - s]);
                sum += ((mp - m + s) & 1) ? -term : term;
            }
            dmat[e] = pref * sum * scale;
        }
        // --- Q (reference's change-of-basis, global phase (-i)^l omitted) ---
        for (int e = tid; e < n * n; e += blockDim.x) { Qre[e] = 0.0; Qim[e] = 0.0; }
        __syncthreads();
        if (tid == 0) {
            const double irt2 = 0.70710678118654752440;
            for (int m = -l; m < 0; m++) {
                Qre[(l + m) * n + (l - m)] = irt2;   // col l+|m|
                Qim[(l + m) * n + (l + m)] = -irt2;  // col l-|m|
            }
            Qre[l * n + l] = 1.0;
            for (int m = 1; m <= l; m++) {
                double sgn = (m & 1) ? -1.0 : 1.0;
                Qre[(l + m) * n + (l + m)] = sgn * irt2;
                Qim[(l + m) * n + (l - m)] = sgn * irt2;
            }
        }
        __syncthreads();
        // --- T2 = (P * d) * Q, P[row mu'] = (-i)^{m'} ---
        for (int e = tid; e < n * n; e += blockDim.x) {
            int i = e / n, b = e % n;
            int mp = i - l;
            int ph = ((mp % 4) + 4) % 4;
            double pre, pim;
            switch (ph) {
                case 0: pre = 1.0;  pim = 0.0;  break;
                case 1: pre = 0.0;  pim = -1.0; break;
                case 2: pre = -1.0; pim = 0.0;  break;
                default: pre = 0.0; pim = 1.0;  break;
            }
            double sre = 0.0, sim = 0.0;
            for (int k = 0; k < n; k++) {
                double t = dmat[i * n + k];
                sre += t * Qre[k * n + b];
                sim += t * Qim[k * n + b];
            }
            T2re[e] = pre * sre - pim * sim;
            T2im[e] = pre * sim + pim * sre;
        }
        __syncthreads();
        // --- G = Re(Q^H T2) ---
        for (int e = tid; e < n * n; e += blockDim.x) {
            int a = e / n, b = e % n;
            double gre = 0.0;
            for (int mu = 0; mu < n; mu++) {
                // conj(Q[mu,a]) * T2[mu,b], keep real part
                gre += Qre[mu * n + a] * T2re[mu * n + b]
                     + Qim[mu * n + a] * T2im[mu * n + b];
            }
            g_G[off + a * n + b] = (float)gre;
        }
        __syncthreads();
    }
}

// ---------------------------------------------------------------------------
// Per-sample Wigner application: out = Yr(a) * G * Yr(-b) * G^T * Yr(g) * s
// ---------------------------------------------------------------------------
template <int L>
__device__ __forceinline__ void apply_wigner(
    const float* __restrict__ G, const float* __restrict__ s,
    const float* cA, const float* sA,
    const float* cB, const float* sB,
    const float* cG, const float* sG,
    float* __restrict__ out)
{
    constexpr int n = 2 * L + 1;
    float u[n], v[n];

    // u = Yr(gamma) s
    u[L] = s[L];
#pragma unroll
    for (int p = 1; p <= L; p++) {
        u[L + p] = cG[p] * s[L + p] - sG[p] * s[L - p];
        u[L - p] = sG[p] * s[L + p] + cG[p] * s[L - p];
    }
    // v = G^T u
#pragma unroll
    for (int i = 0; i < n; i++) v[i] = 0.f;
#pragma unroll
    for (int j = 0; j < n; j++) {
        float uj = u[j];
#pragma unroll
        for (int i = 0; i < n; i++) v[i] += G[j * n + i] * uj;
    }
    // u = Yr(-beta) v
    u[L] = v[L];
#pragma unroll
    for (int p = 1; p <= L; p++) {
        u[L + p] =  cB[p] * v[L + p] + sB[p] * v[L - p];
        u[L - p] = -sB[p] * v[L + p] + cB[p] * v[L - p];
    }
    // v = G u
#pragma unroll
    for (int i = 0; i < n; i++) {
        float acc = 0.f;
#pragma unroll
        for (int j = 0; j < n; j++) acc += G[i * n + j] * u[j];
        v[i] = acc;
    }
    // out = Yr(alpha) v
    out[L] = v[L];
#pragma unroll
    for (int p = 1; p <= L; p++) {
        out[L + p] = cA[p] * v[L + p] - sA[p] * v[L - p];
        out[L - p] = sA[p] * v[L + p] + cA[p] * v[L - p];
    }
}

__global__ __launch_bounds__(256)
void wigner_main_kernel(const float4* __restrict__ quats,
                        const float* __restrict__ s4in,
                        const float* __restrict__ s6in,
                        float* __restrict__ out4,
                        float* __restrict__ out6,
                        int B)
{
    __shared__ float Gs4[81];
    __shared__ float Gs6[169];
    __shared__ float sh4[9], sh6[13];
    __shared__ float stage[256 * 13];

    const int tid = threadIdx.x;
    for (int i = tid; i < 81; i += 256) Gs4[i] = g_G[i];
    for (int i = tid; i < 169; i += 256) Gs6[i] = g_G[81 + i];
    if (tid < 9)  sh4[tid] = s4in[tid];
    if (tid < 13) sh6[tid] = s6in[tid];
    __syncthreads();

    const int blockStart = blockIdx.x * 256;
    const int b = blockStart + tid;
    const bool active = (b < B);

    float o4[9], o6[13];
    if (active) {
        float4 q = quats[b];
        float w = q.x, x = q.y, y = q.z, z = q.w;
        float c   = 2.f * w * w - 1.f;
        float R01 = 2.f * (x * y - w * z);
        float R11 = c + 2.f * y * y;
        float R21 = 2.f * (y * z + w * x);
        float R00 = c + 2.f * x * x;
        float R02 = 2.f * (x * z + w * y);
        float R20 = 2.f * (x * z - w * y);
        float R22 = c + 2.f * z * z;

        // beta from normalized middle column
        float n2 = R01 * R01 + R11 * R11 + R21 * R21;
        float rn = rsqrtf(fmaxf(n2, 1e-24f));
        float cb = fminf(1.f, fmaxf(-1.f, R11 * rn));
        float sb = sqrtf(fmaxf(0.f, 1.f - cb * cb));
        // alpha = atan2(R01, R21)
        float ra2 = R01 * R01 + R21 * R21;
        float ca, sa;
        if (ra2 > 1e-20f) { float r = rsqrtf(ra2); ca = R21 * r; sa = R01 * r; }
        else              { ca = 1.f; sa = 0.f; }
        // gamma = atan2(M02, M00), M[0,j] = ca*R[0,j] - sa*R[2,j]
        float M00 = ca * R00 - sa * R20;
        float M02 = ca * R02 - sa * R22;
        float rg2 = M00 * M00 + M02 * M02;
        float cg, sg;
        if (rg2 > 1e-20f) { float r = rsqrtf(rg2); cg = M00 * r; sg = M02 * r; }
        else              { cg = 1.f; sg = 0.f; }

        // multiples cos(p*theta), sin(p*theta), p = 0..6
        float cA[7], sA[7], cB[7], sB[7], cG[7], sG[7];
        cA[0] = 1.f; sA[0] = 0.f; cB[0] = 1.f; sB[0] = 0.f; cG[0] = 1.f; sG[0] = 0.f;
        cA[1] = ca;  sA[1] = sa;  cB[1] = cb;  sB[1] = sb;  cG[1] = cg;  sG[1] = sg;
#pragma unroll
        for (int p = 2; p < 7; p++) {
            cA[p] = cA[p - 1] * ca - sA[p - 1] * sa;
            sA[p] = sA[p - 1] * ca + cA[p - 1] * sa;
            cB[p] = cB[p - 1] * cb - sB[p - 1] * sb;
            sB[p] = sB[p - 1] * cb + cB[p - 1] * sb;
            cG[p] = cG[p - 1] * cg - sG[p - 1] * sg;
            sG[p] = sG[p - 1] * cg + cG[p - 1] * sg;
        }

        apply_wigner<4>(Gs4, sh4, cA, sA, cB, sB, cG, sG, o4);
        apply_wigner<6>(Gs6, sh6, cA, sA, cB, sB, cG, sG, o6);
    }

    // -------- coalesced output via shared staging --------
    int cnt = B - blockStart;
    if (cnt > 256) cnt = 256;

    if (active) {
#pragma unroll
        for (int i = 0; i < 9; i++) stage[tid * 9 + i] = o4[i];
    }
    __syncthreads();
    for (int k = tid; k < cnt * 9; k += 256) out4[(size_t)blockStart * 9 + k] = stage[k];
    __syncthreads();

    if (active) {
#pragma unroll
        for (int i = 0; i < 13; i++) stage[tid * 13 + i] = o6[i];
    }
    __syncthreads();
    for (int k = tid; k < cnt * 13; k += 256) out6[(size_t)blockStart * 13 + k] = stage[k];
}

extern "C" void kernel_launch(void* const* d_in, const int* in_sizes, int n_in,
                              void* d_out, int out_size)
{
    const float4* quats = (const float4*)d_in[0];
    const float* s4 = (const float*)d_in[1];
    const float* s6 = (const float*)d_in[2];
    // robustness: identify s4/s6 by element count
    if (n_in >= 3 && in_sizes[1] == 13 && in_sizes[2] == 9) {
        const float* t = s4; s4 = s6; s6 = t;
    }
    const int B = in_sizes[0] / 4;
    float* out  = (float*)d_out;
    float* out4 = out;
    float* out6 = out + (size_t)B * 9;

    init_G_kernel<<<1, 256>>>();
    const int grid = (B + 255) / 256;
    wigner_main_kernel<<<grid, 256>>>(quats, s4, s6, out4, out6, B);
}

// round 2
// speedup vs baseline: 3.2222x; 3.2222x over previous
#include <cuda_runtime.h>
#include <cuda_bf16.h>

// ============================================================================
// Compile-time construction of the conjugator matrices
//   G_l = Re(Q^H * P * d(pi/2) * Q)
// so that every matrix element becomes an SASS immediate (FFMA-imm, rt=1)
// and structural zeros are deleted at compile time.
// ============================================================================

__host__ __device__ constexpr double csqrt_c(double x) {
    if (x <= 0.0) return 0.0;
    double s = 1.0;
    while (x > 4.0)  { x *= 0.25; s *= 2.0; }
    while (x < 0.25) { x *= 4.0;  s *= 0.5; }
    double g = 1.0;
    for (int i = 0; i < 30; i++) g = 0.5 * (g + x / g);
    return s * g;
}

struct GMatT {
    double g[169];
    __host__ __device__ constexpr GMatT(int l) : g{} {
        double fact[14] = {};
        fact[0] = 1.0;
        for (int i = 1; i < 14; i++) fact[i] = fact[i - 1] * (double)i;
        const int n = 2 * l + 1;
        double dmat[169] = {}, Qre[169] = {}, Qim[169] = {};
        double T2re[169] = {}, T2im[169] = {};
        double scale = 1.0;
        for (int i = 0; i < l; i++) scale *= 0.5;   // 2^-l

        // Wigner small-d at beta = pi/2
        for (int i = 0; i < n; i++)
            for (int j = 0; j < n; j++) {
                int mp = i - l, m = j - l;
                double pref = csqrt_c(fact[l + mp] * fact[l - mp] *
                                      fact[l + m] * fact[l - m]);
                int smin = (m - mp > 0) ? (m - mp) : 0;
                int smax = (l + m < l - mp) ? (l + m) : (l - mp);
                double sum = 0.0;
                for (int s = smin; s <= smax; s++) {
                    double term = 1.0 / (fact[l + m - s] * fact[s] *
                                         fact[mp - m + s] * fact[l - mp - s]);
                    sum += ((mp - m + s) & 1) ? -term : term;
                }
                dmat[i * n + j] = pref * sum * scale;
            }
        // Q (reference's real->complex basis change, global phase omitted)
        const double irt2 = 0.70710678118654752440084436210485;
        for (int m = -l; m < 0; m++) {
            Qre[(l + m) * n + (l - m)] = irt2;
            Qim[(l + m) * n + (l + m)] = -irt2;
        }
        Qre[l * n + l] = 1.0;
        for (int m = 1; m <= l; m++) {
            double sgn = (m & 1) ? -1.0 : 1.0;
            Qre[(l + m) * n + (l + m)] = sgn * irt2;
            Qim[(l + m) * n + (l - m)] = sgn * irt2;
        }
        // T2 = P * d * Q, with P[row m'] = (-i)^{m'}
        for (int i = 0; i < n; i++) {
            int mp = i - l;
            int ph = ((mp % 4) + 4) % 4;
            double pre = (ph == 0) ? 1.0 : ((ph == 2) ? -1.0 : 0.0);
            double pim = (ph == 1) ? -1.0 : ((ph == 3) ? 1.0 : 0.0);
            for (int b = 0; b < n; b++) {
                double sre = 0.0, sim = 0.0;
                for (int k = 0; k < n; k++) {
                    double t = dmat[i * n + k];
                    sre += t * Qre[k * n + b];
                    sim += t * Qim[k * n + b];
                }
                T2re[i * n + b] = pre * sre - pim * sim;
                T2im[i * n + b] = pre * sim + pim * sre;
            }
        }
        // G = Re(Q^H T2); snap structural zeros
        for (int a = 0; a < n; a++)
            for (int b = 0; b < n; b++) {
                double gre = 0.0;
                for (int mu = 0; mu < n; mu++)
                    gre += Qre[mu * n + a] * T2re[mu * n + b]
                         + Qim[mu * n + a] * T2im[mu * n + b];
                if (gre < 1e-12 && gre > -1e-12) gre = 0.0;
                g[a * n + b] = gre;
            }
    }
};

__host__ __device__ constexpr double getG(int l, int idx) {
    return GMatT(l).g[idx];
}

// ---- fully-unrolled matvec with immediate coefficients + zero deletion ----
template <int L, bool TRANS, int I, int J>
__device__ __forceinline__ float mv_row(const float (&u)[2 * L + 1]) {
    constexpr int n = 2 * L + 1;
    constexpr double gd = getG(L, TRANS ? (J * n + I) : (I * n + J));
    float acc;
    if constexpr (J + 1 < n) acc = mv_row<L, TRANS, I, J + 1>(u);
    else                     acc = 0.0f;
    if constexpr (gd != 0.0) acc = fmaf((float)gd, u[J], acc);
    return acc;
}

template <int L, bool TRANS, int I = 0>
__device__ __forceinline__ void matvec(float (&v)[2 * L + 1],
                                       const float (&u)[2 * L + 1]) {
    v[I] = mv_row<L, TRANS, I, 0>(u);
    if constexpr (I + 1 < 2 * L + 1) matvec<L, TRANS, I + 1>(v, u);
}

// ============================================================================
// Main kernel
// ============================================================================
__global__ void __launch_bounds__(128, 4)
wigner_kernel(const float4* __restrict__ quats,
              const float* __restrict__ s4in,
              const float* __restrict__ s6in,
              float* __restrict__ out4,
              float* __restrict__ out6,
              int B)
{
    __shared__ float shs[22];
    __shared__ float stage[4][32 * 13];

    const int tid = threadIdx.x;
    if (tid < 9)       shs[tid] = s4in[tid];
    else if (tid < 22) shs[tid] = s6in[tid - 9];
    __syncthreads();

    const int warp = tid >> 5, lane = tid & 31;
    const int warpStart = blockIdx.x * 128 + (warp << 5);
    if (warpStart >= B) return;
    const int b = warpStart + lane;
    int cnt = B - warpStart; if (cnt > 32) cnt = 32;

    float4 q = (b < B) ? quats[b] : make_float4(1.f, 0.f, 0.f, 0.f);
    float w = q.x, x = q.y, y = q.z, z = q.w;
    float c   = 2.f * w * w - 1.f;
    float R01 = 2.f * (x * y - w * z);
    float R11 = c + 2.f * y * y;
    float R21 = 2.f * (y * z + w * x);
    float R00 = c + 2.f * x * x;
    float R02 = 2.f * (x * z + w * y);
    float R20 = 2.f * (x * z - w * y);
    float R22 = c + 2.f * z * z;

    // beta from normalized middle column
    float n2 = R01 * R01 + R11 * R11 + R21 * R21;
    float rn = rsqrtf(fmaxf(n2, 1e-24f));
    float cb = fminf(1.f, fmaxf(-1.f, R11 * rn));
    float sb = sqrtf(fmaxf(0.f, 1.f - cb * cb));
    // alpha = atan2(R01, R21)
    float ra2 = R01 * R01 + R21 * R21;
    float ca, sa;
    if (ra2 > 1e-20f) { float r = rsqrtf(ra2); ca = R21 * r; sa = R01 * r; }
    else              { ca = 1.f; sa = 0.f; }
    // gamma = atan2(M02, M00), M[0,j] = ca*R[0,j] - sa*R[2,j]
    float M00 = ca * R00 - sa * R20;
    float M02 = ca * R02 - sa * R22;
    float rg2 = M00 * M00 + M02 * M02;
    float cg, sg;
    if (rg2 > 1e-20f) { float r = rsqrtf(rg2); cg = M00 * r; sg = M02 * r; }
    else              { cg = 1.f; sg = 0.f; }

    // Chebyshev multiples cos(p t), sin(p t), p = 1..6
    float cA[7], sA[7], cB[7], sB[7], cG[7], sG[7];
    cA[1] = ca; sA[1] = sa; cB[1] = cb; sB[1] = sb; cG[1] = cg; sG[1] = sg;
#pragma unroll
    for (int p = 2; p < 7; p++) {
        cA[p] = cA[p - 1] * ca - sA[p - 1] * sa;
        sA[p] = sA[p - 1] * ca + cA[p - 1] * sa;
        cB[p] = cB[p - 1] * cb - sB[p - 1] * sb;
        sB[p] = sB[p - 1] * cb + cB[p - 1] * sb;
        cG[p] = cG[p - 1] * cg - sG[p - 1] * sg;
        sG[p] = sG[p - 1] * cg + cG[p - 1] * sg;
    }

    float* st = stage[warp];

    // ---------------- l = 4 ----------------
    {
        float u[9], v[9], t[9];
        u[4] = shs[4];
#pragma unroll
        for (int p = 1; p <= 4; p++) {
            u[4 + p] = cG[p] * shs[4 + p] - sG[p] * shs[4 - p];
            u[4 - p] = sG[p] * shs[4 + p] + cG[p] * shs[4 - p];
        }
        matvec<4, true>(v, u);      // v = G^T u
        t[4] = v[4];
#pragma unroll
        for (int p = 1; p <= 4; p++) {
            t[4 + p] =  cB[p] * v[4 + p] + sB[p] * v[4 - p];
            t[4 - p] = -sB[p] * v[4 + p] + cB[p] * v[4 - p];
        }
        matvec<4, false>(v, t);     // v = G t
        st[lane * 9 + 4] = v[4];
#pragma unroll
        for (int p = 1; p <= 4; p++) {
            st[lane * 9 + 4 + p] = cA[p] * v[4 + p] - sA[p] * v[4 - p];
            st[lane * 9 + 4 - p] = sA[p] * v[4 + p] + cA[p] * v[4 - p];
        }
    }
    __syncwarp();
    {
        size_t base = (size_t)warpStart * 9;
        for (int k = lane; k < cnt * 9; k += 32) out4[base + k] = st[k];
    }
    __syncwarp();

    // ---------------- l = 6 ----------------
    {
        float u[13], v[13], t[13];
        u[6] = shs[9 + 6];
#pragma unroll
        for (int p = 1; p <= 6; p++) {
            u[6 + p] = cG[p] * shs[9 + 6 + p] - sG[p] * shs[9 + 6 - p];
            u[6 - p] = sG[p] * shs[9 + 6 + p] + cG[p] * shs[9 + 6 - p];
        }
        matvec<6, true>(v, u);      // v = G^T u
        t[6] = v[6];
#pragma unroll
        for (int p = 1; p <= 6; p++) {
            t[6 + p] =  cB[p] * v[6 + p] + sB[p] * v[6 - p];
            t[6 - p] = -sB[p] * v[6 + p] + cB[p] * v[6 - p];
        }
        matvec<6, false>(v, t);     // v = G t
        st[lane * 13 + 6] = v[6];
#pragma unroll
        for (int p = 1; p <= 6; p++) {
            st[lane * 13 + 6 + p] = cA[p] * v[6 + p] - sA[p] * v[6 - p];
            st[lane * 13 + 6 - p] = sA[p] * v[6 + p] + cA[p] * v[6 - p];
        }
    }
    __syncwarp();
    {
        size_t base = (size_t)warpStart * 13;
        for (int k = lane; k < cnt * 13; k += 32) out6[base + k] = st[k];
    }
}

extern "C" void kernel_launch(void* const* d_in, const int* in_sizes, int n_in,
                              void* d_out, int out_size)
{
    const float4* quats = (const float4*)d_in[0];
    const float* s4 = (const float*)d_in[1];
    const float* s6 = (const float*)d_in[2];
    if (n_in >= 3 && in_sizes[1] == 13 && in_sizes[2] == 9) {
        const float* t = s4; s4 = s6; s6 = t;
    }
    const int B = in_sizes[0] / 4;
    float* out  = (float*)d_out;
    float* out4 = out;
    float* out6 = out + (size_t)B * 9;

    const int grid = (B + 127) / 128;
    wigner_kernel<<<grid, 128>>>(quats, s4, s6, out4, out6, B);
}

// round 4
// speedup vs baseline: 3.8119x; 1.1830x over previous
#include <cuda_runtime.h>
#include <cuda_bf16.h>
#include <cstdint>

// ============================================================================
// Compile-time construction of the conjugator matrices
//   G_l = Re(Q^H * P * d(pi/2) * Q)
// Every matrix element becomes a SASS immediate (FFMA src1-imm, rt=1) and
// structural zeros are deleted at compile time.
// ============================================================================

__host__ __device__ constexpr double csqrt_c(double x) {
    if (x <= 0.0) return 0.0;
    double s = 1.0;
    while (x > 4.0)  { x *= 0.25; s *= 2.0; }
    while (x < 0.25) { x *= 4.0;  s *= 0.5; }
    double g = 1.0;
    for (int i = 0; i < 30; i++) g = 0.5 * (g + x / g);
    return s * g;
}

struct GMatT {
    double g[169];
    __host__ __device__ constexpr GMatT(int l) : g{} {
        double fact[14] = {};
        fact[0] = 1.0;
        for (int i = 1; i < 14; i++) fact[i] = fact[i - 1] * (double)i;
        const int n = 2 * l + 1;
        double dmat[169] = {}, Qre[169] = {}, Qim[169] = {};
        double T2re[169] = {}, T2im[169] = {};
        double scale = 1.0;
        for (int i = 0; i < l; i++) scale *= 0.5;   // 2^-l

        for (int i = 0; i < n; i++)
            for (int j = 0; j < n; j++) {
                int mp = i - l, m = j - l;
                double pref = csqrt_c(fact[l + mp] * fact[l - mp] *
                                      fact[l + m] * fact[l - m]);
                int smin = (m - mp > 0) ? (m - mp) : 0;
                int smax = (l + m < l - mp) ? (l + m) : (l - mp);
                double sum = 0.0;
                for (int s = smin; s <= smax; s++) {
                    double term = 1.0 / (fact[l + m - s] * fact[s] *
                                         fact[mp - m + s] * fact[l - mp - s]);
                    sum += ((mp - m + s) & 1) ? -term : term;
                }
                dmat[i * n + j] = pref * sum * scale;
            }
        const double irt2 = 0.70710678118654752440084436210485;
        for (int m = -l; m < 0; m++) {
            Qre[(l + m) * n + (l - m)] = irt2;
            Qim[(l + m) * n + (l + m)] = -irt2;
        }
        Qre[l * n + l] = 1.0;
        for (int m = 1; m <= l; m++) {
            double sgn = (m & 1) ? -1.0 : 1.0;
            Qre[(l + m) * n + (l + m)] = sgn * irt2;
            Qim[(l + m) * n + (l - m)] = sgn * irt2;
        }
        for (int i = 0; i < n; i++) {
            int mp = i - l;
            int ph = ((mp % 4) + 4) % 4;
            double pre = (ph == 0) ? 1.0 : ((ph == 2) ? -1.0 : 0.0);
            double pim = (ph == 1) ? -1.0 : ((ph == 3) ? 1.0 : 0.0);
            for (int b = 0; b < n; b++) {
                double sre = 0.0, sim = 0.0;
                for (int k = 0; k < n; k++) {
                    double t = dmat[i * n + k];
                    sre += t * Qre[k * n + b];
                    sim += t * Qim[k * n + b];
                }
                T2re[i * n + b] = pre * sre - pim * sim;
                T2im[i * n + b] = pre * sim + pim * sre;
            }
        }
        for (int a = 0; a < n; a++)
            for (int b = 0; b < n; b++) {
                double gre = 0.0;
                for (int mu = 0; mu < n; mu++)
                    gre += Qre[mu * n + a] * T2re[mu * n + b]
                         + Qim[mu * n + a] * T2im[mu * n + b];
                if (gre < 1e-12 && gre > -1e-12) gre = 0.0;
                g[a * n + b] = gre;
            }
    }
};

__host__ __device__ constexpr double getG(int l, int idx) {
    return GMatT(l).g[idx];
}

template <int L, bool TRANS, int I, int J>
__device__ __forceinline__ float mv_row(const float (&u)[2 * L + 1]) {
    constexpr int n = 2 * L + 1;
    constexpr double gd = getG(L, TRANS ? (J * n + I) : (I * n + J));
    float acc;
    if constexpr (J + 1 < n) acc = mv_row<L, TRANS, I, J + 1>(u);
    else                     acc = 0.0f;
    if constexpr (gd != 0.0) acc = fmaf((float)gd, u[J], acc);
    return acc;
}

template <int L, bool TRANS, int I = 0>
__device__ __forceinline__ void matvec(float (&v)[2 * L + 1],
                                       const float (&u)[2 * L + 1]) {
    v[I] = mv_row<L, TRANS, I, 0>(u);
    if constexpr (I + 1 < 2 * L + 1) matvec<L, TRANS, I + 1>(v, u);
}

// ============================================================================
// Main kernel: out = Yr(a) * G * Yr(-b) * G^T * Yr(g) * s  for l = 4, 6
// On-the-fly angle multiples (Chebyshev), in-place Y-rotations, float4 staging.
// ============================================================================
__global__ void __launch_bounds__(128, 8)
wigner_kernel(const float4* __restrict__ quats,
              const float* __restrict__ s4in,
              const float* __restrict__ s6in,
              float* __restrict__ out4,
              float* __restrict__ out6,
              int B)
{
    __shared__ float shs[22];
    __shared__ alignas(16) float stage[4][416];

    const int tid = threadIdx.x;
    if (tid < 22) shs[tid] = (tid < 9) ? s4in[tid] : s6in[tid - 9];
    __syncthreads();

    const int warp = tid >> 5, lane = tid & 31;
    const int warpStart = blockIdx.x * 128 + (warp << 5);
    if (warpStart >= B) return;
    const bool full = (warpStart + 32 <= B);
    const int b = warpStart + lane;

    float4 q = (b < B) ? quats[b] : make_float4(1.f, 0.f, 0.f, 0.f);
    float w = q.x, x = q.y, y = q.z, z = q.w;
    float c   = 2.f * w * w - 1.f;
    float R01 = 2.f * (x * y - w * z);
    float R11 = c + 2.f * y * y;
    float R21 = 2.f * (y * z + w * x);
    float R00 = c + 2.f * x * x;
    float R02 = 2.f * (x * z + w * y);
    float R20 = 2.f * (x * z - w * y);
    float R22 = c + 2.f * z * z;

    float n2 = R01 * R01 + R11 * R11 + R21 * R21;
    float rn = rsqrtf(fmaxf(n2, 1e-24f));
    float cb = fminf(1.f, fmaxf(-1.f, R11 * rn));
    float sb = sqrtf(fmaxf(0.f, 1.f - cb * cb));
    float ra2 = R01 * R01 + R21 * R21;
    float ca, sa;
    if (ra2 > 1e-20f) { float r = rsqrtf(ra2); ca = R21 * r; sa = R01 * r; }
    else              { ca = 1.f; sa = 0.f; }
    float M00 = ca * R00 - sa * R20;
    float M02 = ca * R02 - sa * R22;
    float rg2 = M00 * M00 + M02 * M02;
    float cg, sg;
    if (rg2 > 1e-20f) { float r = rsqrtf(rg2); cg = M00 * r; sg = M02 * r; }
    else              { cg = 1.f; sg = 0.f; }

    float* st = stage[warp];

    // ------------------------------- l = 4 --------------------------------
    {
        float u[9], v[9];
        // gamma rotation from shared s4
        {
            float cp = cg, sp = sg;
            u[4] = shs[4];
#pragma unroll
            for (int p = 1; p <= 4; p++) {
                float a_ = shs[4 + p], b_ = shs[4 - p];
                u[4 + p] = cp * a_ - sp * b_;
                u[4 - p] = sp * a_ + cp * b_;
                if (p < 4) { float cn = cp * cg - sp * sg;
                             sp = sp * cg + cp * sg; cp = cn; }
            }
        }
        matvec<4, true>(v, u);          // v = G^T u
        // beta rotation (negative angle), in place
        {
            float cp = cb, sp = sb;
#pragma unroll
            for (int p = 1; p <= 4; p++) {
                float a_ = v[4 + p], b_ = v[4 - p];
                v[4 + p] =  cp * a_ + sp * b_;
                v[4 - p] = -sp * a_ + cp * b_;
                if (p < 4) { float cn = cp * cb - sp * sb;
                             sp = sp * cb + cp * sb; cp = cn; }
            }
        }
        matvec<4, false>(u, v);         // u = G v
        // alpha rotation -> staging
        {
            float cp = ca, sp = sa;
            st[lane * 9 + 4] = u[4];
#pragma unroll
            for (int p = 1; p <= 4; p++) {
                st[lane * 9 + 4 + p] = cp * u[4 + p] - sp * u[4 - p];
                st[lane * 9 + 4 - p] = sp * u[4 + p] + cp * u[4 - p];
                if (p < 4) { float cn = cp * ca - sp * sa;
                             sp = sp * ca + cp * sa; cp = cn; }
            }
        }
    }
    __syncwarp();
    if (full) {
        const float4* sv = (const float4*)st;
        float4* g4 = (float4*)(out4 + (size_t)warpStart * 9);
#pragma unroll
        for (int it = 0; it < 3; it++) {
            int k = lane + 32 * it;
            if (k < 72) g4[k] = sv[k];
        }
    } else {
        int cnt = B - warpStart;
        for (int k = lane; k < cnt * 9; k += 32)
            out4[(size_t)warpStart * 9 + k] = st[k];
    }
    __syncwarp();

    // ------------------------------- l = 6 --------------------------------
    {
        float u[13], v[13];
        {
            float cp = cg, sp = sg;
            u[6] = shs[9 + 6];
#pragma unroll
            for (int p = 1; p <= 6; p++) {
                float a_ = shs[9 + 6 + p], b_ = shs[9 + 6 - p];
                u[6 + p] = cp * a_ - sp * b_;
                u[6 - p] = sp * a_ + cp * b_;
                if (p < 6) { float cn = cp * cg - sp * sg;
                             sp = sp * cg + cp * sg; cp = cn; }
            }
        }
        matvec<6, true>(v, u);          // v = G^T u
        {
            float cp = cb, sp = sb;
#pragma unroll
            for (int p = 1; p <= 6; p++) {
                float a_ = v[6 + p], b_ = v[6 - p];
                v[6 + p] =  cp * a_ + sp * b_;
                v[6 - p] = -sp * a_ + cp * b_;
                if (p < 6) { float cn = cp * cb - sp * sb;
                             sp = sp * cb + cp * sb; cp = cn; }
            }
        }
        matvec<6, false>(u, v);         // u = G v
        {
            float cp = ca, sp = sa;
            st[lane * 13 + 6] = u[6];
#pragma unroll
            for (int p = 1; p <= 6; p++) {
                st[lane * 13 + 6 + p] = cp * u[6 + p] - sp * u[6 - p];
                st[lane * 13 + 6 - p] = sp * u[6 + p] + cp * u[6 - p];
                if (p < 6) { float cn = cp * ca - sp * sa;
                             sp = sp * ca + cp * sa; cp = cn; }
            }
        }
    }
    __syncwarp();
    {
        bool al6 = ((reinterpret_cast<unsigned long long>(out6) & 15ull) == 0ull);
        if (full && al6) {
            const float4* sv = (const float4*)st;
            float4* g6 = (float4*)(out6 + (size_t)warpStart * 13);
#pragma unroll
            for (int it = 0; it < 4; it++) {
                int k = lane + 32 * it;
                if (k < 104) g6[k] = sv[k];
            }
        } else {
            int cnt = B - warpStart; if (cnt > 32) cnt = 32;
            for (int k = lane; k < cnt * 13; k += 32)
                out6[(size_t)warpStart * 13 + k] = st[k];
        }
    }
}

extern "C" void kernel_launch(void* const* d_in, const int* in_sizes, int n_in,
                              void* d_out, int out_size)
{
    const float4* quats = (const float4*)d_in[0];
    const float* s4 = (const float*)d_in[1];
    const float* s6 = (const float*)d_in[2];
    if (n_in >= 3 && in_sizes[1] == 13 && in_sizes[2] == 9) {
        const float* t = s4; s4 = s6; s6 = t;
    }
    const int B = in_sizes[0] / 4;
    float* out  = (float*)d_out;
    float* out4 = out;
    float* out6 = out + (size_t)B * 9;

    const int grid = (B + 127) / 128;
    wigner_kernel<<<grid, 128>>>(quats, s4, s6, out4, out6, B);
}

// round 5
// speedup vs baseline: 3.8570x; 1.0119x over previous
#include <cuda_runtime.h>
#include <cuda_bf16.h>
#include <cstdint>

// ============================================================================
// Compile-time construction of the conjugator matrices
//   G_l = Re(Q^H * P * d(pi/2) * Q)
// Every matrix element becomes a SASS immediate (FFMA src1-imm, rt=1) and
// structural zeros are deleted at compile time.
// ============================================================================

__host__ __device__ constexpr double csqrt_c(double x) {
    if (x <= 0.0) return 0.0;
    double s = 1.0;
    while (x > 4.0)  { x *= 0.25; s *= 2.0; }
    while (x < 0.25) { x *= 4.0;  s *= 0.5; }
    double g = 1.0;
    for (int i = 0; i < 30; i++) g = 0.5 * (g + x / g);
    return s * g;
}

struct GMatT {
    double g[169];
    __host__ __device__ constexpr GMatT(int l) : g{} {
        double fact[14] = {};
        fact[0] = 1.0;
        for (int i = 1; i < 14; i++) fact[i] = fact[i - 1] * (double)i;
        const int n = 2 * l + 1;
        double dmat[169] = {}, Qre[169] = {}, Qim[169] = {};
        double T2re[169] = {}, T2im[169] = {};
        double scale = 1.0;
        for (int i = 0; i < l; i++) scale *= 0.5;   // 2^-l

        for (int i = 0; i < n; i++)
            for (int j = 0; j < n; j++) {
                int mp = i - l, m = j - l;
                double pref = csqrt_c(fact[l + mp] * fact[l - mp] *
                                      fact[l + m] * fact[l - m]);
                int smin = (m - mp > 0) ? (m - mp) : 0;
                int smax = (l + m < l - mp) ? (l + m) : (l - mp);
                double sum = 0.0;
                for (int s = smin; s <= smax; s++) {
                    double term = 1.0 / (fact[l + m - s] * fact[s] *
                                         fact[mp - m + s] * fact[l - mp - s]);
                    sum += ((mp - m + s) & 1) ? -term : term;
                }
                dmat[i * n + j] = pref * sum * scale;
            }
        const double irt2 = 0.70710678118654752440084436210485;
        for (int m = -l; m < 0; m++) {
            Qre[(l + m) * n + (l - m)] = irt2;
            Qim[(l + m) * n + (l + m)] = -irt2;
        }
        Qre[l * n + l] = 1.0;
        for (int m = 1; m <= l; m++) {
            double sgn = (m & 1) ? -1.0 : 1.0;
            Qre[(l + m) * n + (l + m)] = sgn * irt2;
            Qim[(l + m) * n + (l - m)] = sgn * irt2;
        }
        for (int i = 0; i < n; i++) {
            int mp = i - l;
            int ph = ((mp % 4) + 4) % 4;
            double pre = (ph == 0) ? 1.0 : ((ph == 2) ? -1.0 : 0.0);
            double pim = (ph == 1) ? -1.0 : ((ph == 3) ? 1.0 : 0.0);
            for (int b = 0; b < n; b++) {
                double sre = 0.0, sim = 0.0;
                for (int k = 0; k < n; k++) {
                    double t = dmat[i * n + k];
                    sre += t * Qre[k * n + b];
                    sim += t * Qim[k * n + b];
                }
                T2re[i * n + b] = pre * sre - pim * sim;
                T2im[i * n + b] = pre * sim + pim * sre;
            }
        }
        for (int a = 0; a < n; a++)
            for (int b = 0; b < n; b++) {
                double gre = 0.0;
                for (int mu = 0; mu < n; mu++)
                    gre += Qre[mu * n + a] * T2re[mu * n + b]
                         + Qim[mu * n + a] * T2im[mu * n + b];
                if (gre < 1e-12 && gre > -1e-12) gre = 0.0;
                g[a * n + b] = gre;
            }
    }
};

__host__ __device__ constexpr double getG(int l, int idx) {
    return GMatT(l).g[idx];
}

// ---- scalar matvec with immediate coefficients + zero deletion ----
template <int L, bool TRANS, int I, int J>
__device__ __forceinline__ float mv_row(const float (&u)[2 * L + 1]) {
    constexpr int n = 2 * L + 1;
    constexpr double gd = getG(L, TRANS ? (J * n + I) : (I * n + J));
    float acc;
    if constexpr (J + 1 < n) acc = mv_row<L, TRANS, I, J + 1>(u);
    else                     acc = 0.0f;
    if constexpr (gd != 0.0) acc = fmaf((float)gd, u[J], acc);
    return acc;
}

template <int L, bool TRANS, int I = 0>
__device__ __forceinline__ void matvec(float (&v)[2 * L + 1],
                                       const float (&u)[2 * L + 1]) {
    v[I] = mv_row<L, TRANS, I, 0>(u);
    if constexpr (I + 1 < 2 * L + 1) matvec<L, TRANS, I + 1>(v, u);
}

// ============================================================================
// Packed f32x2 helpers (sm_103a): two samples per register pair.
// ============================================================================
typedef unsigned long long u64;
struct f2 { u64 v; };

__device__ __forceinline__ f2 f2pk(float lo, float hi) {
    f2 r; asm("mov.b64 %0,{%1,%2};" : "=l"(r.v) : "f"(lo), "f"(hi)); return r;
}
__device__ __forceinline__ void f2un(f2 p, float& lo, float& hi) {
    asm("mov.b64 {%0,%1},%2;" : "=f"(lo), "=f"(hi) : "l"(p.v));
}
__device__ __forceinline__ f2 f2mul(f2 a, f2 b) {
    f2 r; asm("mul.rn.f32x2 %0,%1,%2;" : "=l"(r.v) : "l"(a.v), "l"(b.v)); return r;
}
__device__ __forceinline__ f2 f2add(f2 a, f2 b) {
    f2 r; asm("add.rn.f32x2 %0,%1,%2;" : "=l"(r.v) : "l"(a.v), "l"(b.v)); return r;
}
__device__ __forceinline__ f2 f2fma(f2 a, f2 b, f2 c) {
    f2 r; asm("fma.rn.f32x2 %0,%1,%2,%3;" : "=l"(r.v) : "l"(a.v), "l"(b.v), "l"(c.v)); return r;
}

// packed matvec: unpack -> 2x scalar imm-FFMA matvec -> repack
template <int L, bool TRANS>
__device__ __forceinline__ void matvec_pk(f2 (&v)[2 * L + 1],
                                          const f2 (&u)[2 * L + 1]) {
    constexpr int n = 2 * L + 1;
    float a[n], b[n], va[n], vb[n];
#pragma unroll
    for (int i = 0; i < n; i++) f2un(u[i], a[i], b[i]);
    matvec<L, TRANS>(va, a);
    matvec<L, TRANS>(vb, b);
#pragma unroll
    for (int i = 0; i < n; i++) v[i] = f2pk(va[i], vb[i]);
}

// ============================================================================
// Main kernel: 2 samples/thread packed; out = Yr(a) G Yr(-b) G^T Yr(g) s
// ============================================================================
__global__ void __launch_bounds__(128, 4)
wigner_kernel(const float4* __restrict__ quats,
              const float* __restrict__ s4in,
              const float* __restrict__ s6in,
              float* __restrict__ out4,
              float* __restrict__ out6,
              int B)
{
    __shared__ alignas(8) float2 shsd[22];           // duplicated (s, s)
    __shared__ alignas(16) float stage[4][64 * 13];

    const int tid = threadIdx.x;
    if (tid < 22) {
        float s = (tid < 9) ? s4in[tid] : s6in[tid - 9];
        shsd[tid] = make_float2(s, s);
    }
    __syncthreads();

    const int warp = tid >> 5, lane = tid & 31;
    const int warpStart = blockIdx.x * 256 + (warp << 6);   // 64 samples / warp
    if (warpStart >= B) return;
    const bool fullw = (warpStart + 64 <= B);
    const int b0 = warpStart + lane;
    const int b1 = b0 + 32;

    float4 q0 = (b0 < B) ? quats[b0] : make_float4(1.f, 0.f, 0.f, 0.f);
    float4 q1 = (b1 < B) ? quats[b1] : make_float4(1.f, 0.f, 0.f, 0.f);

    const f2 NEG1 = f2pk(-1.f, -1.f);

    // ---------------- packed quat -> R ----------------
    f2 W = f2pk(q0.x, q1.x), X = f2pk(q0.y, q1.y);
    f2 Y = f2pk(q0.z, q1.z), Z = f2pk(q0.w, q1.w);

    f2 WW = f2mul(W, W);
    f2 C  = f2add(f2add(WW, WW), NEG1);              // 2w^2 - 1
    f2 XY = f2mul(X, Y), WZ = f2mul(W, Z);
    f2 t01 = f2fma(WZ, NEG1, XY);
    f2 R01 = f2add(t01, t01);
    f2 YZ = f2mul(Y, Z), WX = f2mul(W, X);
    f2 t21 = f2add(YZ, WX);
    f2 R21 = f2add(t21, t21);
    f2 R11 = f2fma(f2add(Y, Y), Y, C);
    f2 R00 = f2fma(f2add(X, X), X, C);
    f2 R22 = f2fma(f2add(Z, Z), Z, C);
    f2 XZ = f2mul(X, Z), WY = f2mul(W, Y);
    f2 t02 = f2add(XZ, WY);
    f2 R02 = f2add(t02, t02);
    f2 t20 = f2fma(WY, NEG1, XZ);
    f2 R20 = f2add(t20, t20);

    // ---------------- angles (scalar halves for MUFU/clamps) --------------
    f2 N2 = f2fma(R01, R01, f2fma(R11, R11, f2mul(R21, R21)));
    float n2a, n2b; f2un(N2, n2a, n2b);
    float R11a, R11b; f2un(R11, R11a, R11b);
    float rna = rsqrtf(fmaxf(n2a, 1e-24f));
    float rnb = rsqrtf(fmaxf(n2b, 1e-24f));
    float cba = fminf(1.f, fmaxf(-1.f, R11a * rna));
    float cbb = fminf(1.f, fmaxf(-1.f, R11b * rnb));
    float sba = sqrtf(fmaxf(0.f, 1.f - cba * cba));
    float sbb = sqrtf(fmaxf(0.f, 1.f - cbb * cbb));
    f2 CB = f2pk(cba, cbb), SB = f2pk(sba, sbb);

    f2 RA2 = f2fma(R01, R01, f2mul(R21, R21));
    float ra2a, ra2b; f2un(RA2, ra2a, ra2b);
    float R01a, R01b; f2un(R01, R01a, R01b);
    float R21a, R21b; f2un(R21, R21a, R21b);
    float caa, saa, cab, sab;
    if (ra2a > 1e-20f) { float r = rsqrtf(ra2a); caa = R21a * r; saa = R01a * r; }
    else               { caa = 1.f; saa = 0.f; }
    if (ra2b > 1e-20f) { float r = rsqrtf(ra2b); cab = R21b * r; sab = R01b * r; }
    else               { cab = 1.f; sab = 0.f; }
    f2 CA = f2pk(caa, cab), SA = f2pk(saa, sab);
    f2 NSA = f2mul(SA, NEG1);

    f2 M00 = f2fma(CA, R00, f2mul(NSA, R20));
    f2 M02 = f2fma(CA, R02, f2mul(NSA, R22));
    f2 RG2 = f2fma(M00, M00, f2mul(M02, M02));
    float rg2a, rg2b; f2un(RG2, rg2a, rg2b);
    float M00a, M00b; f2un(M00, M00a, M00b);
    float M02a, M02b; f2un(M02, M02a, M02b);
    float cga, sga, cgb, sgb;
    if (rg2a > 1e-20f) { float r = rsqrtf(rg2a); cga = M00a * r; sga = M02a * r; }
    else               { cga = 1.f; sga = 0.f; }
    if (rg2b > 1e-20f) { float r = rsqrtf(rg2b); cgb = M00b * r; sgb = M02b * r; }
    else               { cgb = 1.f; sgb = 0.f; }
    f2 CG = f2pk(cga, cgb), SG = f2pk(sga, sgb);

    float* st = stage[warp];
    const u64* shd = reinterpret_cast<const u64*>(shsd);

    // =============================== l = 4 ================================
    {
        f2 u[9], v[9];
        // gamma rotation from shared (packed duplicated)
        {
            f2 cp = CG, sp = SG, nsp = f2mul(SG, NEG1);
            u[4].v = shd[4];
#pragma unroll
            for (int p = 1; p <= 4; p++) {
                f2 a_, b_; a_.v = shd[4 + p]; b_.v = shd[4 - p];
                u[4 + p] = f2fma(cp, a_, f2mul(nsp, b_));
                u[4 - p] = f2fma(sp, a_, f2mul(cp, b_));
                if (p < 4) {
                    f2 cn = f2fma(cp, CG, f2mul(nsp, SG));
                    f2 sn = f2fma(sp, CG, f2mul(cp, SG));
                    cp = cn; sp = sn; nsp = f2mul(sn, NEG1);
                }
            }
        }
        matvec_pk<4, true>(v, u);        // v = G^T u
        // beta rotation (negative angle), in place
        {
            f2 cp = CB, sp = SB, nsp = f2mul(SB, NEG1);
#pragma unroll
            for (int p = 1; p <= 4; p++) {
                f2 a_ = v[4 + p], b_ = v[4 - p];
                v[4 + p] = f2fma(cp, a_, f2mul(sp, b_));
                v[4 - p] = f2fma(cp, b_, f2mul(nsp, a_));
                if (p < 4) {
                    f2 cn = f2fma(cp, CB, f2mul(nsp, SB));
                    f2 sn = f2fma(sp, CB, f2mul(cp, SB));
                    cp = cn; sp = sn; nsp = f2mul(sn, NEG1);
                }
            }
        }
        matvec_pk<4, false>(u, v);       // u = G v
        // alpha rotation -> staging (both halves)
        {
            f2 cp = CA, sp = SA, nsp = NSA;
            float lo, hi;
            f2un(u[4], lo, hi);
            st[lane * 9 + 4] = lo; st[(lane + 32) * 9 + 4] = hi;
#pragma unroll
            for (int p = 1; p <= 4; p++) {
                f2 op = f2fma(cp, u[4 + p], f2mul(nsp, u[4 - p]));
                f2 om = f2fma(sp, u[4 + p], f2mul(cp, u[4 - p]));
                f2un(op, lo, hi);
                st[lane * 9 + 4 + p] = lo; st[(lane + 32) * 9 + 4 + p] = hi;
                f2un(om, lo, hi);
                st[lane * 9 + 4 - p] = lo; st[(lane + 32) * 9 + 4 - p] = hi;
                if (p < 4) {
                    f2 cn = f2fma(cp, CA, f2mul(nsp, SA));
                    f2 sn = f2fma(sp, CA, f2mul(cp, SA));
                    cp = cn; sp = sn; nsp = f2mul(sn, NEG1);
                }
            }
        }
    }
    __syncwarp();
    if (fullw) {
        const float4* sv = (const float4*)st;
        float4* g4 = (float4*)(out4 + (size_t)warpStart * 9);
#pragma unroll
        for (int it = 0; it < 5; it++) {
            int k = lane + 32 * it;
            if (k < 144) g4[k] = sv[k];
        }
    } else {
        int cnt = B - warpStart;
        for (int k = lane; k < cnt * 9; k += 32)
            out4[(size_t)warpStart * 9 + k] = st[k];
    }
    __syncwarp();

    // =============================== l = 6 ================================
    {
        f2 u[13], v[13];
        {
            f2 cp = CG, sp = SG, nsp = f2mul(SG, NEG1);
            u[6].v = shd[9 + 6];
#pragma unroll
            for (int p = 1; p <= 6; p++) {
                f2 a_, b_; a_.v = shd[9 + 6 + p]; b_.v = shd[9 + 6 - p];
                u[6 + p] = f2fma(cp, a_, f2mul(nsp, b_));
                u[6 - p] = f2fma(sp, a_, f2mul(cp, b_));
                if (p < 6) {
                    f2 cn = f2fma(cp, CG, f2mul(nsp, SG));
                    f2 sn = f2fma(sp, CG, f2mul(cp, SG));
                    cp = cn; sp = sn; nsp = f2mul(sn, NEG1);
                }
            }
        }
        matvec_pk<6, true>(v, u);        // v = G^T u
        {
            f2 cp = CB, sp = SB, nsp = f2mul(SB, NEG1);
#pragma unroll
            for (int p = 1; p <= 6; p++) {
                f2 a_ = v[6 + p], b_ = v[6 - p];
                v[6 + p] = f2fma(cp, a_, f2mul(sp, b_));
                v[6 - p] = f2fma(cp, b_, f2mul(nsp, a_));
                if (p < 6) {
                    f2 cn = f2fma(cp, CB, f2mul(nsp, SB));
                    f2 sn = f2fma(sp, CB, f2mul(cp, SB));
                    cp = cn; sp = sn; nsp = f2mul(sn, NEG1);
                }
            }
        }
        matvec_pk<6, false>(u, v);       // u = G v
        {
            f2 cp = CA, sp = SA, nsp = NSA;
            float lo, hi;
            f2un(u[6], lo, hi);
            st[lane * 13 + 6] = lo; st[(lane + 32) * 13 + 6] = hi;
#pragma unroll
            for (int p = 1; p <= 6; p++) {
                f2 op = f2fma(cp, u[6 + p], f2mul(nsp, u[6 - p]));
                f2 om = f2fma(sp, u[6 + p], f2mul(cp, u[6 - p]));
                f2un(op, lo, hi);
                st[lane * 13 + 6 + p] = lo; st[(lane + 32) * 13 + 6 + p] = hi;
                f2un(om, lo, hi);
                st[lane * 13 + 6 - p] = lo; st[(lane + 32) * 13 + 6 - p] = hi;
                if (p < 6) {
                    f2 cn = f2fma(cp, CA, f2mul(nsp, SA));
                    f2 sn = f2fma(sp, CA, f2mul(cp, SA));
                    cp = cn; sp = sn; nsp = f2mul(sn, NEG1);
                }
            }
        }
    }
    __syncwarp();
    if (fullw) {
        const float4* sv = (const float4*)st;
        float4* g6 = (float4*)(out6 + (size_t)warpStart * 13);
#pragma unroll
        for (int it = 0; it < 7; it++) {
            int k = lane + 32 * it;
            if (k < 208) g6[k] = sv[k];
        }
    } else {
        int cnt = B - warpStart;
        for (int k = lane; k < cnt * 13; k += 32)
            out6[(size_t)warpStart * 13 + k] = st[k];
    }
}

extern "C" void kernel_launch(void* const* d_in, const int* in_sizes, int n_in,
                              void* d_out, int out_size)
{
    const float4* quats = (const float4*)d_in[0];
    const float* s4 = (const float*)d_in[1];
    const float* s6 = (const float*)d_in[2];
    if (n_in >= 3 && in_sizes[1] == 13 && in_sizes[2] == 9) {
        const float* t = s4; s4 = s6; s6 = t;
    }
    const int B = in_sizes[0] / 4;
    float* out  = (float*)d_out;
    float* out4 = out;
    float* out6 = out + (size_t)B * 9;

    const int grid = (B + 255) / 256;
    wigner_kernel<<<grid, 256 / 2>>>(quats, s4, s6, out4, out6, B);
}

// round 6
// speedup vs baseline: 4.0208x; 1.0425x over previous
#include <cuda_runtime.h>
#include <cuda_bf16.h>
#include <cstdint>

// ============================================================================
// Compile-time construction of the conjugator matrices
//   G_l = Re(Q^H * P * d(pi/2) * Q)
// Every matrix element becomes a SASS immediate (FFMA src1-imm, rt=1) and
// structural zeros are deleted at compile time.
// ============================================================================

__host__ __device__ constexpr double csqrt_c(double x) {
    if (x <= 0.0) return 0.0;
    double s = 1.0;
    while (x > 4.0)  { x *= 0.25; s *= 2.0; }
    while (x < 0.25) { x *= 4.0;  s *= 0.5; }
    double g = 1.0;
    for (int i = 0; i < 30; i++) g = 0.5 * (g + x / g);
    return s * g;
}

struct GMatT {
    double g[169];
    __host__ __device__ constexpr GMatT(int l) : g{} {
        double fact[14] = {};
        fact[0] = 1.0;
        for (int i = 1; i < 14; i++) fact[i] = fact[i - 1] * (double)i;
        const int n = 2 * l + 1;
        double dmat[169] = {}, Qre[169] = {}, Qim[169] = {};
        double T2re[169] = {}, T2im[169] = {};
        double scale = 1.0;
        for (int i = 0; i < l; i++) scale *= 0.5;   // 2^-l

        for (int i = 0; i < n; i++)
            for (int j = 0; j < n; j++) {
                int mp = i - l, m = j - l;
                double pref = csqrt_c(fact[l + mp] * fact[l - mp] *
                                      fact[l + m] * fact[l - m]);
                int smin = (m - mp > 0) ? (m - mp) : 0;
                int smax = (l + m < l - mp) ? (l + m) : (l - mp);
                double sum = 0.0;
                for (int s = smin; s <= smax; s++) {
                    double term = 1.0 / (fact[l + m - s] * fact[s] *
                                         fact[mp - m + s] * fact[l - mp - s]);
                    sum += ((mp - m + s) & 1) ? -term : term;
                }
                dmat[i * n + j] = pref * sum * scale;
            }
        const double irt2 = 0.70710678118654752440084436210485;
        for (int m = -l; m < 0; m++) {
            Qre[(l + m) * n + (l - m)] = irt2;
            Qim[(l + m) * n + (l + m)] = -irt2;
        }
        Qre[l * n + l] = 1.0;
        for (int m = 1; m <= l; m++) {
            double sgn = (m & 1) ? -1.0 : 1.0;
            Qre[(l + m) * n + (l + m)] = sgn * irt2;
            Qim[(l + m) * n + (l - m)] = sgn * irt2;
        }
        for (int i = 0; i < n; i++) {
            int mp = i - l;
            int ph = ((mp % 4) + 4) % 4;
            double pre = (ph == 0) ? 1.0 : ((ph == 2) ? -1.0 : 0.0);
            double pim = (ph == 1) ? -1.0 : ((ph == 3) ? 1.0 : 0.0);
            for (int b = 0; b < n; b++) {
                double sre = 0.0, sim = 0.0;
                for (int k = 0; k < n; k++) {
                    double t = dmat[i * n + k];
                    sre += t * Qre[k * n + b];
                    sim += t * Qim[k * n + b];
                }
                T2re[i * n + b] = pre * sre - pim * sim;
                T2im[i * n + b] = pre * sim + pim * sre;
            }
        }
        for (int a = 0; a < n; a++)
            for (int b = 0; b < n; b++) {
                double gre = 0.0;
                for (int mu = 0; mu < n; mu++)
                    gre += Qre[mu * n + a] * T2re[mu * n + b]
                         + Qim[mu * n + a] * T2im[mu * n + b];
                if (gre < 1e-12 && gre > -1e-12) gre = 0.0;
                g[a * n + b] = gre;
            }
    }
};

__host__ __device__ constexpr double getG(int l, int idx) {
    return GMatT(l).g[idx];
}

template <int L, bool TRANS, int I, int J>
__device__ __forceinline__ float mv_row(const float (&u)[2 * L + 1]) {
    constexpr int n = 2 * L + 1;
    constexpr double gd = getG(L, TRANS ? (J * n + I) : (I * n + J));
    float acc;
    if constexpr (J + 1 < n) acc = mv_row<L, TRANS, I, J + 1>(u);
    else                     acc = 0.0f;
    if constexpr (gd != 0.0) acc = fmaf((float)gd, u[J], acc);
    return acc;
}

template <int L, bool TRANS, int I = 0>
__device__ __forceinline__ void matvec(float (&v)[2 * L + 1],
                                       const float (&u)[2 * L + 1]) {
    v[I] = mv_row<L, TRANS, I, 0>(u);
    if constexpr (I + 1 < 2 * L + 1) matvec<L, TRANS, I + 1>(v, u);
}

// ============================================================================
// Main kernel: out = Yr(a) * G * Yr(-b) * G^T * Yr(g) * s  for l = 4, 6
// Streaming loads/stores (.cs) to keep the 176MB of write-once output from
// thrashing L2. On-the-fly Chebyshev multiples, float4 staged stores.
// ============================================================================
__global__ void __launch_bounds__(128, 8)
wigner_kernel(const float4* __restrict__ quats,
              const float* __restrict__ s4in,
              const float* __restrict__ s6in,
              float* __restrict__ out4,
              float* __restrict__ out6,
              int B)
{
    __shared__ float shs[22];
    __shared__ alignas(16) float stage[4][416];

    const int tid = threadIdx.x;
    if (tid < 22) shs[tid] = (tid < 9) ? s4in[tid] : s6in[tid - 9];
    __syncthreads();

    const int warp = tid >> 5, lane = tid & 31;
    const int warpStart = blockIdx.x * 128 + (warp << 5);
    if (warpStart >= B) return;
    const bool full = (warpStart + 32 <= B);
    const int b = warpStart + lane;

    float4 q = (b < B) ? __ldcs(&quats[b]) : make_float4(1.f, 0.f, 0.f, 0.f);
    float w = q.x, x = q.y, y = q.z, z = q.w;
    float c   = 2.f * w * w - 1.f;
    float R01 = 2.f * (x * y - w * z);
    float R11 = c + 2.f * y * y;
    float R21 = 2.f * (y * z + w * x);
    float R00 = c + 2.f * x * x;
    float R02 = 2.f * (x * z + w * y);
    float R20 = 2.f * (x * z - w * y);
    float R22 = c + 2.f * z * z;

    float n2 = R01 * R01 + R11 * R11 + R21 * R21;
    float rn = rsqrtf(fmaxf(n2, 1e-24f));
    float cb = fminf(1.f, fmaxf(-1.f, R11 * rn));
    float sb = sqrtf(fmaxf(0.f, 1.f - cb * cb));
    float ra2 = R01 * R01 + R21 * R21;
    float ca, sa;
    if (ra2 > 1e-20f) { float r = rsqrtf(ra2); ca = R21 * r; sa = R01 * r; }
    else              { ca = 1.f; sa = 0.f; }
    float M00 = ca * R00 - sa * R20;
    float M02 = ca * R02 - sa * R22;
    float rg2 = M00 * M00 + M02 * M02;
    float cg, sg;
    if (rg2 > 1e-20f) { float r = rsqrtf(rg2); cg = M00 * r; sg = M02 * r; }
    else              { cg = 1.f; sg = 0.f; }

    float* st = stage[warp];

    // ------------------------------- l = 4 --------------------------------
    {
        float u[9], v[9];
        {
            float cp = cg, sp = sg;
            u[4] = shs[4];
#pragma unroll
            for (int p = 1; p <= 4; p++) {
                float a_ = shs[4 + p], b_ = shs[4 - p];
                u[4 + p] = cp * a_ - sp * b_;
                u[4 - p] = sp * a_ + cp * b_;
                if (p < 4) { float cn = cp * cg - sp * sg;
                             sp = sp * cg + cp * sg; cp = cn; }
            }
        }
        matvec<4, true>(v, u);          // v = G^T u
        {
            float cp = cb, sp = sb;
#pragma unroll
            for (int p = 1; p <= 4; p++) {
                float a_ = v[4 + p], b_ = v[4 - p];
                v[4 + p] =  cp * a_ + sp * b_;
                v[4 - p] = -sp * a_ + cp * b_;
                if (p < 4) { float cn = cp * cb - sp * sb;
                             sp = sp * cb + cp * sb; cp = cn; }
            }
        }
        matvec<4, false>(u, v);         // u = G v
        {
            float cp = ca, sp = sa;
            st[lane * 9 + 4] = u[4];
#pragma unroll
            for (int p = 1; p <= 4; p++) {
                st[lane * 9 + 4 + p] = cp * u[4 + p] - sp * u[4 - p];
                st[lane * 9 + 4 - p] = sp * u[4 + p] + cp * u[4 - p];
                if (p < 4) { float cn = cp * ca - sp * sa;
                             sp = sp * ca + cp * sa; cp = cn; }
            }
        }
    }
    __syncwarp();
    if (full) {
        const float4* sv = (const float4*)st;
        float4* g4 = (float4*)(out4 + (size_t)warpStart * 9);
#pragma unroll
        for (int it = 0; it < 3; it++) {
            int k = lane + 32 * it;
            if (k < 72) __stcs(&g4[k], sv[k]);
        }
    } else {
        int cnt = B - warpStart;
        for (int k = lane; k < cnt * 9; k += 32)
            __stcs(&out4[(size_t)warpStart * 9 + k], st[k]);
    }
    __syncwarp();

    // ------------------------------- l = 6 --------------------------------
    {
        float u[13], v[13];
        {
            float cp = cg, sp = sg;
            u[6] = shs[9 + 6];
#pragma unroll
            for (int p = 1; p <= 6; p++) {
                float a_ = shs[9 + 6 + p], b_ = shs[9 + 6 - p];
                u[6 + p] = cp * a_ - sp * b_;
                u[6 - p] = sp * a_ + cp * b_;
                if (p < 6) { float cn = cp * cg - sp * sg;
                             sp = sp * cg + cp * sg; cp = cn; }
            }
        }
        matvec<6, true>(v, u);          // v = G^T u
        {
            float cp = cb, sp = sb;
#pragma unroll
            for (int p = 1; p <= 6; p++) {
                float a_ = v[6 + p], b_ = v[6 - p];
                v[6 + p] =  cp * a_ + sp * b_;
                v[6 - p] = -sp * a_ + cp * b_;
                if (p < 6) { float cn = cp * cb - sp * sb;
                             sp = sp * cb + cp * sb; cp = cn; }
            }
        }
        matvec<6, false>(u, v);         // u = G v
        {
            float cp = ca, sp = sa;
            st[lane * 13 + 6] = u[6];
#pragma unroll
            for (int p = 1; p <= 6; p++) {
                st[lane * 13 + 6 + p] = cp * u[6 + p] - sp * u[6 - p];
                st[lane * 13 + 6 - p] = sp * u[6 + p] + cp * u[6 - p];
                if (p < 6) { float cn = cp * ca - sp * sa;
                             sp = sp * ca + cp * sa; cp = cn; }
            }
        }
    }
    __syncwarp();
    {
        bool al6 = ((reinterpret_cast<unsigned long long>(out6) & 15ull) == 0ull);
        if (full && al6) {
            const float4* sv = (const float4*)st;
            float4* g6 = (float4*)(out6 + (size_t)warpStart * 13);
#pragma unroll
            for (int it = 0; it < 4; it++) {
                int k = lane + 32 * it;
                if (k < 104) __stcs(&g6[k], sv[k]);
            }
        } else {
            int cnt = B - warpStart; if (cnt > 32) cnt = 32;
            for (int k = lane; k < cnt * 13; k += 32)
                __stcs(&out6[(size_t)warpStart * 13 + k], st[k]);
        }
    }
}

extern "C" void kernel_launch(void* const* d_in, const int* in_sizes, int n_in,
                              void* d_out, int out_size)
{
    const float4* quats = (const float4*)d_in[0];
    const float* s4 = (const float*)d_in[1];
    const float* s6 = (const float*)d_in[2];
    if (n_in >= 3 && in_sizes[1] == 13 && in_sizes[2] == 9) {
        const float* t = s4; s4 = s6; s6 = t;
    }
    const int B = in_sizes[0] / 4;
    float* out  = (float*)d_out;
    float* out4 = out;
    float* out6 = out + (size_t)B * 9;

    const int grid = (B + 127) / 128;
    wigner_kernel<<<grid, 128>>>(quats, s4, s6, out4, out6, B);
}